// round 15
// baseline (speedup 1.0000x reference)
#include <cuda_runtime.h>
#include <cuda_bf16.h>

#define DD 128
#define MAXN 100000
#define MAXE 1700000
#define MAXES 131072
#define NREL 16
#define SCAN_CHUNK 1024
#define MAX_CHUNKS ((MAXN + SCAN_CHUNK - 1) / SCAN_CHUNK)

#define WROW 136
#define IMG_U32 (DD * (WROW / 2))   // 8704 u32 per 128x136 bf16 image

typedef unsigned long long u64;
typedef unsigned int u32;

static __device__ __align__(16) float g_dinv[MAXN];
static __device__ __align__(256) float g_h[MAXN * DD];
static __device__ __align__(256) float g_agg[MAXN * DD];
static __device__ int g_deg[MAXN];
static __device__ int g_rowptr[MAXN + 1];
static __device__ int g_cur[MAXN];
static __device__ int g_srcs[MAXE];
static __device__ int g_blksum[MAX_CHUNKS];
static __device__ int g_cnt[NREL];
static __device__ int g_off[NREL + 1];
static __device__ int g_rcur[NREL];
static __device__ int g_bucket[MAXES];
static __device__ unsigned char g_flag[MAXN];
static __device__ __align__(16) u32 g_w1h[IMG_U32];
static __device__ __align__(16) u32 g_w1l[IMG_U32];
static __device__ __align__(16) u32 g_w2h[IMG_U32];
static __device__ __align__(16) u32 g_w2l[IMG_U32];
static __device__ __align__(16) u32 g_rwh[NREL * IMG_U32];
static __device__ __align__(16) u32 g_rwl[NREL * IMG_U32];

// ===========================================================================
// helpers
// ===========================================================================
__device__ __forceinline__ u32 smem_u32(const void* p) {
    u32 a;
    asm("{ .reg .u64 t; cvta.to.shared.u64 t, %1; cvt.u32.u64 %0, t; }"
        : "=r"(a) : "l"(p));
    return a;
}

#define LDSM_X4(r, addr) \
    asm volatile("ldmatrix.sync.aligned.m8n8.x4.shared.b16 {%0,%1,%2,%3}, [%4];" \
                 : "=r"((r)[0]), "=r"((r)[1]), "=r"((r)[2]), "=r"((r)[3]) \
                 : "r"(addr))

__device__ __forceinline__ void mma_bf16(float* c, const u32* a, u32 b0, u32 b1) {
    asm volatile(
        "mma.sync.aligned.m16n8k16.row.col.f32.bf16.bf16.f32 "
        "{%0,%1,%2,%3}, {%4,%5,%6,%7}, {%8,%9}, {%0,%1,%2,%3};"
        : "+f"(c[0]), "+f"(c[1]), "+f"(c[2]), "+f"(c[3])
        : "r"(a[0]), "r"(a[1]), "r"(a[2]), "r"(a[3]), "r"(b0), "r"(b1));
}

__device__ __forceinline__ void split_pack(float a0, float a1, u32& hi, u32& lo) {
    __nv_bfloat16 h0 = __float2bfloat16(a0);
    __nv_bfloat16 h1 = __float2bfloat16(a1);
    __nv_bfloat16 l0 = __float2bfloat16(a0 - __bfloat162float(h0));
    __nv_bfloat16 l1 = __float2bfloat16(a1 - __bfloat162float(h1));
    hi = (u32)__bfloat16_as_ushort(h0) | ((u32)__bfloat16_as_ushort(h1) << 16);
    lo = (u32)__bfloat16_as_ushort(l0) | ((u32)__bfloat16_as_ushort(l1) << 16);
}

// ===========================================================================
// prep (stream 0): deg count | rel count + flags
// ===========================================================================
__global__ void prep_edges_kernel(const int* __restrict__ dst, int E,
                                  const int* __restrict__ rel,
                                  const int* __restrict__ head,
                                  const int* __restrict__ tail, int ES) {
    int nbE = (E + 1023) / 1024;
    int b = blockIdx.x;
    int tid = threadIdx.x;
    if (b < nbE) {
#pragma unroll
        for (int i = 0; i < 4; i++) {
            int e = b * 1024 + i * 256 + tid;
            if (e < E) atomicAdd(&g_deg[dst[e]], 1);
        }
    } else {
#pragma unroll
        for (int i = 0; i < 4; i++) {
            int e = (b - nbE) * 1024 + i * 256 + tid;
            if (e < ES) {
                atomicAdd(&g_cnt[rel[e]], 1);
                g_flag[head[e]] = 1;
                g_flag[tail[e]] = 1;
            }
        }
    }
}

// W1/W2 split (side stream, feeds GEMM1/GEMM2)
__global__ void prep_w_kernel(const float* __restrict__ W1,
                              const float* __restrict__ W2) {
    int id = blockIdx.x * blockDim.x + threadIdx.x;  // 0..16383
    const float* W = (id < 8192) ? W1 : W2;
    u32* oh = (id < 8192) ? g_w1h : g_w2h;
    u32* ol = (id < 8192) ? g_w1l : g_w2l;
    int wi = id & 8191;
    int nrow = wi >> 6;
    int kp = wi & 63;
    int k = kp * 2;
    float a0 = W[k * DD + nrow];
    float a1 = W[(k + 1) * DD + nrow];
    u32 hi, lo;
    split_pack(a0, a1, hi, lo);
    int idx = nrow * (WROW / 2) + kp;
    oh[idx] = hi;
    ol[idx] = lo;
    if (kp < 4) {
        oh[nrow * (WROW / 2) + 64 + kp] = 0u;
        ol[nrow * (WROW / 2) + 64 + kp] = 0u;
    }
}

// relW split (side stream; only score consumes it)
__global__ void prep_relw_kernel(const float* __restrict__ relW) {
    int id = blockIdx.x * blockDim.x + threadIdx.x;  // 0..131071
    int r = id >> 13;
    int wi = id & 8191;
    int nrow = wi >> 6;
    int kp = wi & 63;
    int k = kp * 2;
    const float* W = relW + (size_t)r * DD * DD;
    float a0 = W[k * DD + nrow];
    float a1 = W[(k + 1) * DD + nrow];
    u32 hi, lo;
    split_pack(a0, a1, hi, lo);
    int idx = r * IMG_U32 + nrow * (WROW / 2) + kp;
    g_rwh[idx] = hi;
    g_rwl[idx] = lo;
    if (kp < 4) {
        g_rwh[r * IMG_U32 + nrow * (WROW / 2) + 64 + kp] = 0u;
        g_rwl[r * IMG_U32 + nrow * (WROW / 2) + 64 + kp] = 0u;
    }
}

// ===========================================================================
// Scan kernels for CSR rowptr (+ relation prefix folded into scan2)
// ===========================================================================
__global__ void scan1_kernel(int n) {
    __shared__ int wsum[8];
    int chunk = blockIdx.x;
    int tid = threadIdx.x;
    int s = 0;
#pragma unroll
    for (int i = 0; i < 4; i++) {
        int idx = chunk * SCAN_CHUNK + tid + i * 256;
        if (idx < n) s += g_deg[idx];
    }
#pragma unroll
    for (int off = 16; off; off >>= 1) s += __shfl_down_sync(0xffffffffu, s, off);
    if ((tid & 31) == 0) wsum[tid >> 5] = s;
    __syncthreads();
    if (tid == 0) {
        int a = 0;
#pragma unroll
        for (int i = 0; i < 8; i++) a += wsum[i];
        g_blksum[chunk] = a;
    }
}

__global__ void scan2_kernel(int nchunks, int n) {
    int tid = threadIdx.x;
    if (tid < 32) {
        int v[4];
        int s = 0;
#pragma unroll
        for (int j = 0; j < 4; j++) {
            int idx = tid * 4 + j;
            v[j] = (idx < nchunks) ? g_blksum[idx] : 0;
            s += v[j];
        }
        int pre = s;
#pragma unroll
        for (int off = 1; off < 32; off <<= 1) {
            int t = __shfl_up_sync(0xffffffffu, pre, off);
            if (tid >= off) pre += t;
        }
        int run = pre - s;
#pragma unroll
        for (int j = 0; j < 4; j++) {
            int idx = tid * 4 + j;
            if (idx < nchunks) g_blksum[idx] = run;
            run += v[j];
        }
        if (tid == 31) g_rowptr[n] = run;
    } else if (tid == 32) {
        int acc = 0;
        for (int i = 0; i < NREL; i++) {
            g_off[i] = acc;
            g_rcur[i] = acc;
            acc += g_cnt[i];
        }
        g_off[NREL] = acc;
    }
}

__global__ void scan3_kernel(int n) {
    __shared__ int wsum[8];
    int chunk = blockIdx.x;
    int tid = threadIdx.x;
    int lane = tid & 31, w = tid >> 5;
    int base0 = chunk * SCAN_CHUNK + tid * 4;
    int v[4];
    int s = 0;
#pragma unroll
    for (int j = 0; j < 4; j++) {
        int idx = base0 + j;
        v[j] = (idx < n) ? g_deg[idx] : 0;
        s += v[j];
    }
    int pre = s;
#pragma unroll
    for (int off = 1; off < 32; off <<= 1) {
        int t = __shfl_up_sync(0xffffffffu, pre, off);
        if (lane >= off) pre += t;
    }
    if (lane == 31) wsum[w] = pre;
    __syncthreads();
    if (tid == 0) {
        int a = 0;
#pragma unroll
        for (int i = 0; i < 8; i++) { int t = wsum[i]; wsum[i] = a; a += t; }
    }
    __syncthreads();
    int excl = pre - s + wsum[w] + g_blksum[chunk];
#pragma unroll
    for (int j = 0; j < 4; j++) {
        int idx = base0 + j;
        if (idx < n) {
            g_rowptr[idx] = excl;
            g_cur[idx] = excl;
            g_dinv[idx] = (v[j] > 0) ? rsqrtf((float)v[j]) : 0.0f;
            excl += v[j];
        }
    }
}

// fused: CSR placement | relation bucket placement (4 items / thread)
__global__ void place_kernel(const int* __restrict__ src,
                             const int* __restrict__ dst, int E,
                             const int* __restrict__ rel, int ES) {
    int nbE = (E + 1023) / 1024;
    int b = blockIdx.x;
    int tid = threadIdx.x;
    if (b < nbE) {
#pragma unroll
        for (int i = 0; i < 4; i++) {
            int e = b * 1024 + i * 256 + tid;
            if (e < E) {
                int pos = atomicAdd(&g_cur[dst[e]], 1);
                g_srcs[pos] = src[e];
            }
        }
    } else {
#pragma unroll
        for (int i = 0; i < 4; i++) {
            int e = (b - nbE) * 1024 + i * 256 + tid;
            if (e < ES) {
                int pos = atomicAdd(&g_rcur[rel[e]], 1);
                g_bucket[pos] = e;
            }
        }
    }
}

// ===========================================================================
// Tensor-core GEMM (mma.sync, bf16 3-pass split), warp tile 32m x 64n.
// FUSE_IN:  a -> relu(dinv[row]*a + b1)
// SCALE_OUT: out row *= dinv[row]  (GEMM2 only; lets gather2 skip dinv loads)
// ===========================================================================
template <bool FUSE_IN, bool SCALE_OUT>
__global__ __launch_bounds__(256, 1)
void gemm_mma_kernel(const float* __restrict__ A, const float* __restrict__ bias,
                     const u32* __restrict__ WhImg, const u32* __restrict__ WlImg,
                     float* __restrict__ out, int n) {
    extern __shared__ __align__(16) char sm[];
    char* Ah = sm;                        // 128*272
    char* Al = sm + 34816;
    char* Wh = sm + 2 * 34816;
    char* Wl = sm + 3 * 34816;

    int tid = threadIdx.x;
    {
        const float4* wh4 = (const float4*)WhImg;
        const float4* wl4 = (const float4*)WlImg;
        float4* dh = (float4*)Wh;
        float4* dl = (float4*)Wl;
#pragma unroll
        for (int i = 0; i < 9; i++) {
            int v = tid + i * 256;
            if (v < 2176) {
                dh[v] = wh4[v];
                dl[v] = wl4[v];
            }
        }
    }

    int row0 = blockIdx.x * 128;
#pragma unroll
    for (int i = 0; i < 16; i++) {
        int v = tid + i * 256;
        int r = v >> 5;
        int c4 = v & 31;
        int grow = row0 + r;
        float4 a = make_float4(0.f, 0.f, 0.f, 0.f);
        if (grow < n) {
            a = ((const float4*)A)[(size_t)grow * 32 + c4];
            if (FUSE_IN) {
                float di = g_dinv[grow];
                int c = c4 * 4;
                a.x = fmaxf(di * a.x + bias[c + 0], 0.f);
                a.y = fmaxf(di * a.y + bias[c + 1], 0.f);
                a.z = fmaxf(di * a.z + bias[c + 2], 0.f);
                a.w = fmaxf(di * a.w + bias[c + 3], 0.f);
            }
        }
        u32 h0, l0, h1, l1;
        split_pack(a.x, a.y, h0, l0);
        split_pack(a.z, a.w, h1, l1);
        int boff = r * 272 + c4 * 8;
        *(u64*)(Ah + boff) = (u64)h0 | ((u64)h1 << 32);
        *(u64*)(Al + boff) = (u64)l0 | ((u64)l1 << 32);
    }
    __syncthreads();

    int w = tid >> 5;
    int lane = tid & 31;
    int wm = w >> 1;
    int wn = w & 1;
    int m0 = 32 * wm;
    int n0 = 64 * wn;

    int arow = (lane & 7) + (lane & 8);
    int acolb = (lane & 16);
    u32 aAh0 = smem_u32(Ah) + (m0 + arow) * 272 + acolb;
    u32 aAl0 = smem_u32(Al) + (m0 + arow) * 272 + acolb;
    u32 aAh1 = aAh0 + 16 * 272;
    u32 aAl1 = aAl0 + 16 * 272;
    int brow = (lane & 7) + ((lane & 16) >> 1);
    int bcolb = (lane & 8) * 2;
    u32 aWh = smem_u32(Wh) + (n0 + brow) * 272 + bcolb;
    u32 aWl = smem_u32(Wl) + (n0 + brow) * 272 + bcolb;

    float acc[16][4];
#pragma unroll
    for (int t = 0; t < 16; t++)
#pragma unroll
        for (int q = 0; q < 4; q++) acc[t][q] = 0.f;

#pragma unroll
    for (int ks = 0; ks < 8; ks++) {
        u32 koff = ks * 32;
        u32 ah0[4], ah1[4], al0[4], al1[4];
        LDSM_X4(ah0, aAh0 + koff);
        LDSM_X4(ah1, aAh1 + koff);
        LDSM_X4(al0, aAl0 + koff);
        LDSM_X4(al1, aAl1 + koff);
#pragma unroll
        for (int nt = 0; nt < 4; nt++) {
            u32 noff = nt * 16 * 272;
            u32 bh[4], bl[4];
            LDSM_X4(bh, aWh + noff + koff);
            LDSM_X4(bl, aWl + noff + koff);
            int j0 = 2 * nt, j1 = 2 * nt + 1;
            mma_bf16(acc[j0],     ah0, bh[0], bh[1]);
            mma_bf16(acc[j0],     ah0, bl[0], bl[1]);
            mma_bf16(acc[j0],     al0, bh[0], bh[1]);
            mma_bf16(acc[j1],     ah0, bh[2], bh[3]);
            mma_bf16(acc[j1],     ah0, bl[2], bl[3]);
            mma_bf16(acc[j1],     al0, bh[2], bh[3]);
            mma_bf16(acc[8 + j0], ah1, bh[0], bh[1]);
            mma_bf16(acc[8 + j0], ah1, bl[0], bl[1]);
            mma_bf16(acc[8 + j0], al1, bh[0], bh[1]);
            mma_bf16(acc[8 + j1], ah1, bh[2], bh[3]);
            mma_bf16(acc[8 + j1], ah1, bl[2], bl[3]);
            mma_bf16(acc[8 + j1], al1, bh[2], bh[3]);
        }
    }

    int colb = 2 * (lane & 3);
#pragma unroll
    for (int i = 0; i < 2; i++) {
        int grow0 = row0 + m0 + 16 * i + (lane >> 2);
        int grow1 = grow0 + 8;
        float d0 = 1.f, d1 = 1.f;
        if (SCALE_OUT) {
            d0 = (grow0 < n) ? g_dinv[grow0] : 0.f;
            d1 = (grow1 < n) ? g_dinv[grow1] : 0.f;
        }
#pragma unroll
        for (int j = 0; j < 8; j++) {
            int col = n0 + j * 8 + colb;
            if (grow0 < n)
                *(float2*)&out[(size_t)grow0 * DD + col] =
                    make_float2(acc[i * 8 + j][0] * d0, acc[i * 8 + j][1] * d0);
            if (grow1 < n)
                *(float2*)&out[(size_t)grow1 * DD + col] =
                    make_float2(acc[i * 8 + j][2] * d1, acc[i * 8 + j][3] * d1);
        }
    }
}

// ===========================================================================
// CSR gather: agg[v] = sum_{e in csr(v)} w(src)*h[src]
//   USE_DINV: w = dinv[src] (layer 1; h1 unscaled)
//   else:     w = 1         (layer 2; h2 pre-scaled by dinv in GEMM2 epilogue)
// ===========================================================================
template <bool FLAGGED, bool USE_DINV>
__global__ void gather_kernel(const float4* __restrict__ h4,
                              float4* __restrict__ agg4, int n) {
    int v = (blockIdx.x * blockDim.x + threadIdx.x) >> 5;
    int lane = threadIdx.x & 31;
    if (v >= n) return;
    if (FLAGGED && !g_flag[v]) return;
    int beg = g_rowptr[v];
    int end = g_rowptr[v + 1];
    float4 acc = make_float4(0.f, 0.f, 0.f, 0.f);
    int i = beg;
    for (; i + 8 <= end; i += 8) {
        int s[8];
#pragma unroll
        for (int q = 0; q < 8; q++) s[q] = __ldg(&g_srcs[i + q]);
        float ds[8];
#pragma unroll
        for (int q = 0; q < 8; q++) ds[q] = USE_DINV ? __ldg(&g_dinv[s[q]]) : 1.f;
        float4 a[8];
#pragma unroll
        for (int q = 0; q < 8; q++) a[q] = __ldg(&h4[(size_t)s[q] * 32 + lane]);
#pragma unroll
        for (int q = 0; q < 8; q++) {
            if (USE_DINV) {
                acc.x += ds[q] * a[q].x; acc.y += ds[q] * a[q].y;
                acc.z += ds[q] * a[q].z; acc.w += ds[q] * a[q].w;
            } else {
                acc.x += a[q].x; acc.y += a[q].y;
                acc.z += a[q].z; acc.w += a[q].w;
            }
        }
    }
    for (; i < end; i++) {
        int s = __ldg(&g_srcs[i]);
        float ds = USE_DINV ? __ldg(&g_dinv[s]) : 1.f;
        float4 a = __ldg(&h4[(size_t)s * 32 + lane]);
        if (USE_DINV) {
            acc.x += ds * a.x; acc.y += ds * a.y;
            acc.z += ds * a.z; acc.w += ds * a.w;
        } else {
            acc.x += a.x; acc.y += a.y; acc.z += a.z; acc.w += a.w;
        }
    }
    agg4[(size_t)v * 32 + lane] = acc;
}

// ===========================================================================
// Scoring (relation-grouped, MMA): out[e] = zh^T W[r] zt
// z = dinv*agg + b2 per row (agg = gather2 output, dst-dinv NOT yet applied)
// ===========================================================================
__global__ __launch_bounds__(256, 1)
void score_kernel(const float* __restrict__ z,
                  const float* __restrict__ b2,
                  const int* __restrict__ head,
                  const int* __restrict__ tail,
                  float* __restrict__ out, int ES) {
    extern __shared__ __align__(16) char sm[];
    char* Zh = sm;                            // 64*272 bf16 hi
    char* Zl = sm + 17408;                    // 64*272 bf16 lo
    char* Wh = sm + 34816;                    // 128*272
    char* Wl = sm + 69632;                    // 128*272
    float* Zt = (float*)(sm + 104448);        // 64*128 f32
    float* Cc = (float*)(sm + 137216);        // 64*128 f32
    __shared__ int s_eid[64];
    __shared__ int s_head[64];
    __shared__ int s_tail[64];
    __shared__ __align__(16) float s_b2[DD];

    int r = blockIdx.x;
    int beg = g_off[r], end = g_off[r + 1];
    int base = beg + (int)blockIdx.y * 64;
    if (base >= end) return;
    int nb = min(64, end - base);
    int tid = threadIdx.x;

    {
        const float4* wh4 = (const float4*)(g_rwh + (size_t)r * IMG_U32);
        const float4* wl4 = (const float4*)(g_rwl + (size_t)r * IMG_U32);
        float4* dh = (float4*)Wh;
        float4* dl = (float4*)Wl;
#pragma unroll
        for (int i = 0; i < 9; i++) {
            int v = tid + i * 256;
            if (v < 2176) {
                dh[v] = __ldg(&wh4[v]);
                dl[v] = __ldg(&wl4[v]);
            }
        }
    }
    if (tid < DD) s_b2[tid] = b2[tid];
    if (tid < 64) {
        int e = -1, hh = 0, tt = 0;
        if (tid < nb) {
            e = g_bucket[base + tid];
            hh = __ldg(&head[e]);
            tt = __ldg(&tail[e]);
        }
        s_eid[tid] = e; s_head[tid] = hh; s_tail[tid] = tt;
    }
    __syncthreads();

    const float4* z4 = (const float4*)z;
    const float4* b24 = (const float4*)s_b2;
#pragma unroll
    for (int i = 0; i < 8; i++) {
        int v = tid + i * 256;
        int rr = v >> 5, c4 = v & 31;
        float4 ah = make_float4(0.f, 0.f, 0.f, 0.f);
        float4 at = make_float4(0.f, 0.f, 0.f, 0.f);
        if (rr < nb) {
            int hh = s_head[rr], tt = s_tail[rr];
            float dh_ = g_dinv[hh], dt_ = g_dinv[tt];
            float4 xh = __ldg(&z4[(size_t)hh * 32 + c4]);
            float4 xt = __ldg(&z4[(size_t)tt * 32 + c4]);
            float4 b = b24[c4];
            ah.x = dh_ * xh.x + b.x; ah.y = dh_ * xh.y + b.y;
            ah.z = dh_ * xh.z + b.z; ah.w = dh_ * xh.w + b.w;
            at.x = dt_ * xt.x + b.x; at.y = dt_ * xt.y + b.y;
            at.z = dt_ * xt.z + b.z; at.w = dt_ * xt.w + b.w;
        }
        u32 h0, l0, h1, l1;
        split_pack(ah.x, ah.y, h0, l0);
        split_pack(ah.z, ah.w, h1, l1);
        int boff = rr * 272 + c4 * 8;
        *(u64*)(Zh + boff) = (u64)h0 | ((u64)h1 << 32);
        *(u64*)(Zl + boff) = (u64)l0 | ((u64)l1 << 32);
        ((float4*)Zt)[v] = at;
    }
    __syncthreads();

    int w = tid >> 5;
    int lane = tid & 31;
    int wm = w >> 1;
    int wn = w & 1;
    int m0 = 16 * wm;
    int n0 = 64 * wn;

    int arow = (lane & 7) + (lane & 8);
    int acolb = (lane & 16);
    u32 aZh = smem_u32(Zh) + (m0 + arow) * 272 + acolb;
    u32 aZl = smem_u32(Zl) + (m0 + arow) * 272 + acolb;
    int brow = (lane & 7) + ((lane & 16) >> 1);
    int bcolb = (lane & 8) * 2;
    u32 aWh = smem_u32(Wh) + (n0 + brow) * 272 + bcolb;
    u32 aWl = smem_u32(Wl) + (n0 + brow) * 272 + bcolb;

    float acc[8][4];
#pragma unroll
    for (int t = 0; t < 8; t++)
#pragma unroll
        for (int q = 0; q < 4; q++) acc[t][q] = 0.f;

#pragma unroll
    for (int ks = 0; ks < 8; ks++) {
        u32 koff = ks * 32;
        u32 ah[4], al[4];
        LDSM_X4(ah, aZh + koff);
        LDSM_X4(al, aZl + koff);
#pragma unroll
        for (int nt = 0; nt < 4; nt++) {
            u32 noff = nt * 16 * 272;
            u32 bh[4], bl[4];
            LDSM_X4(bh, aWh + noff + koff);
            LDSM_X4(bl, aWl + noff + koff);
            int j0 = 2 * nt, j1 = j0 + 1;
            mma_bf16(acc[j0], ah, bh[0], bh[1]);
            mma_bf16(acc[j0], ah, bl[0], bl[1]);
            mma_bf16(acc[j0], al, bh[0], bh[1]);
            mma_bf16(acc[j1], ah, bh[2], bh[3]);
            mma_bf16(acc[j1], ah, bl[2], bl[3]);
            mma_bf16(acc[j1], al, bh[2], bh[3]);
        }
    }

    int mrow = m0 + (lane >> 2);
    int colb = 2 * (lane & 3);
#pragma unroll
    for (int j = 0; j < 8; j++) {
        int col = n0 + j * 8 + colb;
        *(float2*)&Cc[mrow * DD + col]       = make_float2(acc[j][0], acc[j][1]);
        *(float2*)&Cc[(mrow + 8) * DD + col] = make_float2(acc[j][2], acc[j][3]);
    }
    __syncthreads();

#pragma unroll
    for (int rr8 = 0; rr8 < 8; rr8++) {
        int row = w * 8 + rr8;
        float4 c = ((float4*)Cc)[row * 32 + lane];
        float4 t = ((float4*)Zt)[row * 32 + lane];
        float p = c.x * t.x + c.y * t.y + c.z * t.z + c.w * t.w;
#pragma unroll
        for (int off = 16; off; off >>= 1)
            p += __shfl_down_sync(0xffffffffu, p, off);
        if (lane == 0 && row < nb) out[s_eid[row]] = p;
    }
}

// ---------------------------------------------------------------------------
extern "C" void kernel_launch(void* const* d_in, const int* in_sizes, int n_in,
                              void* d_out, int out_size) {
    const float* x0   = (const float*)d_in[0];
    const float* W1   = (const float*)d_in[1];
    const float* b1   = (const float*)d_in[2];
    const float* W2   = (const float*)d_in[3];
    const float* b2   = (const float*)d_in[4];
    const float* relW = (const float*)d_in[5];
    const int*   ei   = (const int*)d_in[6];
    const int*   rel  = (const int*)d_in[7];
    const int*   head = (const int*)d_in[8];
    const int*   tail = (const int*)d_in[9];

    int N  = in_sizes[0] / DD;
    int E  = in_sizes[6] / 2;
    int ES = in_sizes[7];
    const int* src = ei;
    const int* dst = ei + E;

    float *h_p, *agg_p;
    int *deg_p, *cnt_p;
    unsigned char* flag_p;
    u32 *w1h_p, *w1l_p, *w2h_p, *w2l_p;
    cudaGetSymbolAddress((void**)&h_p, g_h);
    cudaGetSymbolAddress((void**)&agg_p, g_agg);
    cudaGetSymbolAddress((void**)&deg_p, g_deg);
    cudaGetSymbolAddress((void**)&cnt_p, g_cnt);
    cudaGetSymbolAddress((void**)&flag_p, g_flag);
    cudaGetSymbolAddress((void**)&w1h_p, g_w1h);
    cudaGetSymbolAddress((void**)&w1l_p, g_w1l);
    cudaGetSymbolAddress((void**)&w2h_p, g_w2h);
    cudaGetSymbolAddress((void**)&w2l_p, g_w2l);

    size_t gemm_smem = 4 * 34816;       // 136 KB
    size_t score_smem = 169984;         // ~166 KB
    cudaFuncSetAttribute(score_kernel,
                         cudaFuncAttributeMaxDynamicSharedMemorySize, (int)score_smem);
    cudaFuncSetAttribute((gemm_mma_kernel<false, false>),
                         cudaFuncAttributeMaxDynamicSharedMemorySize, (int)gemm_smem);
    cudaFuncSetAttribute((gemm_mma_kernel<true, true>),
                         cudaFuncAttributeMaxDynamicSharedMemorySize, (int)gemm_smem);

    // side streams + events, created once on the first (non-capture) call
    struct Side {
        cudaStream_t s2, s3;
        cudaEvent_t evStart, evScan3, evPlace, evG1, evRelw;
        Side() {
            cudaStreamCreateWithFlags(&s2, cudaStreamNonBlocking);
            cudaStreamCreateWithFlags(&s3, cudaStreamNonBlocking);
            cudaEventCreateWithFlags(&evStart, cudaEventDisableTiming);
            cudaEventCreateWithFlags(&evScan3, cudaEventDisableTiming);
            cudaEventCreateWithFlags(&evPlace, cudaEventDisableTiming);
            cudaEventCreateWithFlags(&evG1, cudaEventDisableTiming);
            cudaEventCreateWithFlags(&evRelw, cudaEventDisableTiming);
        }
    };
    static Side side;

    int nchunks = (N + SCAN_CHUNK - 1) / SCAN_CHUNK;
    int nbE4 = (E + 1023) / 1024;
    int nbS4 = (ES + 1023) / 1024;
    int gemm_blocks = (N + 127) / 128;
    int gather_blocks = (N * 32 + 255) / 256;

    // fork side pipeline FIRST: W split -> GEMM1 -> relW split
    cudaEventRecord(side.evStart, 0);
    cudaStreamWaitEvent(side.s3, side.evStart, 0);
    prep_w_kernel<<<64, 256, 0, side.s3>>>(W1, W2);
    gemm_mma_kernel<false, false><<<gemm_blocks, 256, gemm_smem, side.s3>>>(
        x0, nullptr, w1h_p, w1l_p, h_p, N);
    cudaEventRecord(side.evG1, side.s3);
    prep_relw_kernel<<<512, 256, 0, side.s3>>>(relW);
    cudaEventRecord(side.evRelw, side.s3);

    // main stream: CSR front-end
    cudaMemsetAsync(deg_p, 0, (size_t)N * sizeof(int), 0);
    cudaMemsetAsync(cnt_p, 0, NREL * sizeof(int), 0);
    cudaMemsetAsync(flag_p, 0, (size_t)N, 0);
    prep_edges_kernel<<<nbE4 + nbS4, 256>>>(dst, E, rel, head, tail, ES);
    scan1_kernel<<<nchunks, 256>>>(N);
    scan2_kernel<<<1, 64>>>(nchunks, N);
    scan3_kernel<<<nchunks, 256>>>(N);

    // placement forked onto s2
    cudaEventRecord(side.evScan3, 0);
    cudaStreamWaitEvent(side.s2, side.evScan3, 0);
    place_kernel<<<nbE4 + nbS4, 256, 0, side.s2>>>(src, dst, E, rel, ES);
    cudaEventRecord(side.evPlace, side.s2);

    // join GEMM1 + place, then gather1 (dinv-weighted)
    cudaStreamWaitEvent(0, side.evG1, 0);
    cudaStreamWaitEvent(0, side.evPlace, 0);
    gather_kernel<false, true><<<gather_blocks, 256>>>((const float4*)h_p,
                                                       (float4*)agg_p, N);

    // GEMM2: h2 = dinv * (relu(dinv*agg + b1) @ W2) -> g_h (dinv pre-applied)
    gemm_mma_kernel<true, true><<<gemm_blocks, 256, gemm_smem>>>(
        agg_p, b1, w2h_p, w2l_p, h_p, N);

    // flagged gather2 (no dinv loads): z rows -> g_agg
    gather_kernel<true, false><<<gather_blocks, 256>>>((const float4*)h_p,
                                                       (float4*)agg_p, N);

    // join relW prep, then score (reads z from g_agg)
    cudaStreamWaitEvent(0, side.evRelw, 0);
    {
        dim3 grid(NREL, (ES + 63) / 64);
        score_kernel<<<grid, 256, score_smem>>>(agg_p, b2, head, tail,
                                                (float*)d_out, ES);
    }
}

// round 16
// speedup vs baseline: 1.1211x; 1.1211x over previous
#include <cuda_runtime.h>
#include <cuda_bf16.h>

#define DD 128
#define MAXN 100000
#define MAXE 1700000
#define MAXES 131072
#define NREL 16
#define SCAN_CHUNK 1024
#define MAX_CHUNKS ((MAXN + SCAN_CHUNK - 1) / SCAN_CHUNK)

#define WROW 136
#define IMG_U32 (DD * (WROW / 2))   // 8704 u32 per 128x136 bf16 image

typedef unsigned long long u64;
typedef unsigned int u32;

static __device__ __align__(16) float g_dinv[MAXN];
static __device__ __align__(256) float g_h[MAXN * DD];
static __device__ __align__(256) float g_agg[MAXN * DD];
static __device__ int g_deg[MAXN];
static __device__ int g_rowptr[MAXN + 1];
static __device__ int g_cur[MAXN];
static __device__ int g_srcs[MAXE];
static __device__ int g_blksum[MAX_CHUNKS];
static __device__ int g_cnt[NREL];
static __device__ int g_off[NREL + 1];
static __device__ int g_rcur[NREL];
static __device__ int g_bucket[MAXES];
static __device__ unsigned char g_flag[MAXN];
static __device__ __align__(16) u32 g_w1h[IMG_U32];
static __device__ __align__(16) u32 g_w1l[IMG_U32];
static __device__ __align__(16) u32 g_w2h[IMG_U32];
static __device__ __align__(16) u32 g_w2l[IMG_U32];
static __device__ __align__(16) u32 g_rwh[NREL * IMG_U32];
static __device__ __align__(16) u32 g_rwl[NREL * IMG_U32];

// ===========================================================================
// helpers
// ===========================================================================
__device__ __forceinline__ u32 smem_u32(const void* p) {
    u32 a;
    asm("{ .reg .u64 t; cvta.to.shared.u64 t, %1; cvt.u32.u64 %0, t; }"
        : "=r"(a) : "l"(p));
    return a;
}

#define LDSM_X4(r, addr) \
    asm volatile("ldmatrix.sync.aligned.m8n8.x4.shared.b16 {%0,%1,%2,%3}, [%4];" \
                 : "=r"((r)[0]), "=r"((r)[1]), "=r"((r)[2]), "=r"((r)[3]) \
                 : "r"(addr))

__device__ __forceinline__ void mma_bf16(float* c, const u32* a, u32 b0, u32 b1) {
    asm volatile(
        "mma.sync.aligned.m16n8k16.row.col.f32.bf16.bf16.f32 "
        "{%0,%1,%2,%3}, {%4,%5,%6,%7}, {%8,%9}, {%0,%1,%2,%3};"
        : "+f"(c[0]), "+f"(c[1]), "+f"(c[2]), "+f"(c[3])
        : "r"(a[0]), "r"(a[1]), "r"(a[2]), "r"(a[3]), "r"(b0), "r"(b1));
}

__device__ __forceinline__ void split_pack(float a0, float a1, u32& hi, u32& lo) {
    __nv_bfloat16 h0 = __float2bfloat16(a0);
    __nv_bfloat16 h1 = __float2bfloat16(a1);
    __nv_bfloat16 l0 = __float2bfloat16(a0 - __bfloat162float(h0));
    __nv_bfloat16 l1 = __float2bfloat16(a1 - __bfloat162float(h1));
    hi = (u32)__bfloat16_as_ushort(h0) | ((u32)__bfloat16_as_ushort(h1) << 16);
    lo = (u32)__bfloat16_as_ushort(l0) | ((u32)__bfloat16_as_ushort(l1) << 16);
}

// ===========================================================================
// prep (stream 0): deg count | rel count + flags
// ===========================================================================
__global__ void prep_edges_kernel(const int* __restrict__ dst, int E,
                                  const int* __restrict__ rel,
                                  const int* __restrict__ head,
                                  const int* __restrict__ tail, int ES) {
    int nbE = (E + 1023) / 1024;
    int b = blockIdx.x;
    int tid = threadIdx.x;
    if (b < nbE) {
#pragma unroll
        for (int i = 0; i < 4; i++) {
            int e = b * 1024 + i * 256 + tid;
            if (e < E) atomicAdd(&g_deg[dst[e]], 1);
        }
    } else {
#pragma unroll
        for (int i = 0; i < 4; i++) {
            int e = (b - nbE) * 1024 + i * 256 + tid;
            if (e < ES) {
                atomicAdd(&g_cnt[rel[e]], 1);
                g_flag[head[e]] = 1;
                g_flag[tail[e]] = 1;
            }
        }
    }
}

// W1/W2 split (side stream, feeds GEMM1/GEMM2)
__global__ void prep_w_kernel(const float* __restrict__ W1,
                              const float* __restrict__ W2) {
    int id = blockIdx.x * blockDim.x + threadIdx.x;  // 0..16383
    const float* W = (id < 8192) ? W1 : W2;
    u32* oh = (id < 8192) ? g_w1h : g_w2h;
    u32* ol = (id < 8192) ? g_w1l : g_w2l;
    int wi = id & 8191;
    int nrow = wi >> 6;
    int kp = wi & 63;
    int k = kp * 2;
    float a0 = W[k * DD + nrow];
    float a1 = W[(k + 1) * DD + nrow];
    u32 hi, lo;
    split_pack(a0, a1, hi, lo);
    int idx = nrow * (WROW / 2) + kp;
    oh[idx] = hi;
    ol[idx] = lo;
    if (kp < 4) {
        oh[nrow * (WROW / 2) + 64 + kp] = 0u;
        ol[nrow * (WROW / 2) + 64 + kp] = 0u;
    }
}

// relW split (side stream; only score consumes it)
__global__ void prep_relw_kernel(const float* __restrict__ relW) {
    int id = blockIdx.x * blockDim.x + threadIdx.x;  // 0..131071
    int r = id >> 13;
    int wi = id & 8191;
    int nrow = wi >> 6;
    int kp = wi & 63;
    int k = kp * 2;
    const float* W = relW + (size_t)r * DD * DD;
    float a0 = W[k * DD + nrow];
    float a1 = W[(k + 1) * DD + nrow];
    u32 hi, lo;
    split_pack(a0, a1, hi, lo);
    int idx = r * IMG_U32 + nrow * (WROW / 2) + kp;
    g_rwh[idx] = hi;
    g_rwl[idx] = lo;
    if (kp < 4) {
        g_rwh[r * IMG_U32 + nrow * (WROW / 2) + 64 + kp] = 0u;
        g_rwl[r * IMG_U32 + nrow * (WROW / 2) + 64 + kp] = 0u;
    }
}

// ===========================================================================
// Scan kernels for CSR rowptr (+ relation prefix folded into scan2)
// ===========================================================================
__global__ void scan1_kernel(int n) {
    __shared__ int wsum[8];
    int chunk = blockIdx.x;
    int tid = threadIdx.x;
    int s = 0;
#pragma unroll
    for (int i = 0; i < 4; i++) {
        int idx = chunk * SCAN_CHUNK + tid + i * 256;
        if (idx < n) s += g_deg[idx];
    }
#pragma unroll
    for (int off = 16; off; off >>= 1) s += __shfl_down_sync(0xffffffffu, s, off);
    if ((tid & 31) == 0) wsum[tid >> 5] = s;
    __syncthreads();
    if (tid == 0) {
        int a = 0;
#pragma unroll
        for (int i = 0; i < 8; i++) a += wsum[i];
        g_blksum[chunk] = a;
    }
}

__global__ void scan2_kernel(int nchunks, int n) {
    int tid = threadIdx.x;
    if (tid < 32) {
        int v[4];
        int s = 0;
#pragma unroll
        for (int j = 0; j < 4; j++) {
            int idx = tid * 4 + j;
            v[j] = (idx < nchunks) ? g_blksum[idx] : 0;
            s += v[j];
        }
        int pre = s;
#pragma unroll
        for (int off = 1; off < 32; off <<= 1) {
            int t = __shfl_up_sync(0xffffffffu, pre, off);
            if (tid >= off) pre += t;
        }
        int run = pre - s;
#pragma unroll
        for (int j = 0; j < 4; j++) {
            int idx = tid * 4 + j;
            if (idx < nchunks) g_blksum[idx] = run;
            run += v[j];
        }
        if (tid == 31) g_rowptr[n] = run;
    } else if (tid == 32) {
        int acc = 0;
        for (int i = 0; i < NREL; i++) {
            g_off[i] = acc;
            g_rcur[i] = acc;
            acc += g_cnt[i];
        }
        g_off[NREL] = acc;
    }
}

__global__ void scan3_kernel(int n) {
    __shared__ int wsum[8];
    int chunk = blockIdx.x;
    int tid = threadIdx.x;
    int lane = tid & 31, w = tid >> 5;
    int base0 = chunk * SCAN_CHUNK + tid * 4;
    int v[4];
    int s = 0;
#pragma unroll
    for (int j = 0; j < 4; j++) {
        int idx = base0 + j;
        v[j] = (idx < n) ? g_deg[idx] : 0;
        s += v[j];
    }
    int pre = s;
#pragma unroll
    for (int off = 1; off < 32; off <<= 1) {
        int t = __shfl_up_sync(0xffffffffu, pre, off);
        if (lane >= off) pre += t;
    }
    if (lane == 31) wsum[w] = pre;
    __syncthreads();
    if (tid == 0) {
        int a = 0;
#pragma unroll
        for (int i = 0; i < 8; i++) { int t = wsum[i]; wsum[i] = a; a += t; }
    }
    __syncthreads();
    int excl = pre - s + wsum[w] + g_blksum[chunk];
#pragma unroll
    for (int j = 0; j < 4; j++) {
        int idx = base0 + j;
        if (idx < n) {
            g_rowptr[idx] = excl;
            g_cur[idx] = excl;
            g_dinv[idx] = (v[j] > 0) ? rsqrtf((float)v[j]) : 0.0f;
            excl += v[j];
        }
    }
}

// fused: CSR placement | relation bucket placement (4 items / thread)
__global__ void place_kernel(const int* __restrict__ src,
                             const int* __restrict__ dst, int E,
                             const int* __restrict__ rel, int ES) {
    int nbE = (E + 1023) / 1024;
    int b = blockIdx.x;
    int tid = threadIdx.x;
    if (b < nbE) {
#pragma unroll
        for (int i = 0; i < 4; i++) {
            int e = b * 1024 + i * 256 + tid;
            if (e < E) {
                int pos = atomicAdd(&g_cur[dst[e]], 1);
                g_srcs[pos] = src[e];
            }
        }
    } else {
#pragma unroll
        for (int i = 0; i < 4; i++) {
            int e = (b - nbE) * 1024 + i * 256 + tid;
            if (e < ES) {
                int pos = atomicAdd(&g_rcur[rel[e]], 1);
                g_bucket[pos] = e;
            }
        }
    }
}

// ===========================================================================
// Tensor-core GEMM (mma.sync, bf16 3-pass split).
// 64-row tiles, 2 CTAs/SM: block B's staging overlaps block A's MMA.
// 8 warps, warp tile 16m x 64n (4x2 grid).
// FUSE_IN: a -> relu(dinv[row]*a + b1).
// ===========================================================================
template <bool FUSE_IN>
__global__ __launch_bounds__(256, 2)
void gemm_mma_kernel(const float* __restrict__ A, const float* __restrict__ bias,
                     const u32* __restrict__ WhImg, const u32* __restrict__ WlImg,
                     float* __restrict__ out, int n) {
    extern __shared__ __align__(16) char sm[];
    char* Ah = sm;                        // 64*272 = 17408
    char* Al = sm + 17408;
    char* Wh = sm + 34816;                // 128*272 = 34816
    char* Wl = sm + 69632;

    int tid = threadIdx.x;
    {
        const float4* wh4 = (const float4*)WhImg;
        const float4* wl4 = (const float4*)WlImg;
        float4* dh = (float4*)Wh;
        float4* dl = (float4*)Wl;
#pragma unroll
        for (int i = 0; i < 9; i++) {
            int v = tid + i * 256;
            if (v < 2176) {
                dh[v] = wh4[v];
                dl[v] = wl4[v];
            }
        }
    }

    int row0 = blockIdx.x * 64;
#pragma unroll
    for (int i = 0; i < 8; i++) {
        int v = tid + i * 256;          // 0..2047
        int r = v >> 5;                 // row in tile (0..63)
        int c4 = v & 31;
        int grow = row0 + r;
        float4 a = make_float4(0.f, 0.f, 0.f, 0.f);
        if (grow < n) {
            a = ((const float4*)A)[(size_t)grow * 32 + c4];
            if (FUSE_IN) {
                float di = g_dinv[grow];
                int c = c4 * 4;
                a.x = fmaxf(di * a.x + bias[c + 0], 0.f);
                a.y = fmaxf(di * a.y + bias[c + 1], 0.f);
                a.z = fmaxf(di * a.z + bias[c + 2], 0.f);
                a.w = fmaxf(di * a.w + bias[c + 3], 0.f);
            }
        }
        u32 h0, l0, h1, l1;
        split_pack(a.x, a.y, h0, l0);
        split_pack(a.z, a.w, h1, l1);
        int boff = r * 272 + c4 * 8;
        *(u64*)(Ah + boff) = (u64)h0 | ((u64)h1 << 32);
        *(u64*)(Al + boff) = (u64)l0 | ((u64)l1 << 32);
    }
    __syncthreads();

    int w = tid >> 5;
    int lane = tid & 31;
    int wm = w >> 1;   // 0..3 -> m-strip of 16
    int wn = w & 1;    // 0..1 -> n-strip of 64
    int m0 = 16 * wm;
    int n0 = 64 * wn;

    int arow = (lane & 7) + (lane & 8);
    int acolb = (lane & 16);
    u32 aAh = smem_u32(Ah) + (m0 + arow) * 272 + acolb;
    u32 aAl = smem_u32(Al) + (m0 + arow) * 272 + acolb;
    int brow = (lane & 7) + ((lane & 16) >> 1);
    int bcolb = (lane & 8) * 2;
    u32 aWh = smem_u32(Wh) + (n0 + brow) * 272 + bcolb;
    u32 aWl = smem_u32(Wl) + (n0 + brow) * 272 + bcolb;

    float acc[8][4];
#pragma unroll
    for (int t = 0; t < 8; t++)
#pragma unroll
        for (int q = 0; q < 4; q++) acc[t][q] = 0.f;

#pragma unroll
    for (int ks = 0; ks < 8; ks++) {
        u32 koff = ks * 32;
        u32 ah[4], al[4];
        LDSM_X4(ah, aAh + koff);
        LDSM_X4(al, aAl + koff);
#pragma unroll
        for (int nt = 0; nt < 4; nt++) {
            u32 noff = nt * 16 * 272;
            u32 bh[4], bl[4];
            LDSM_X4(bh, aWh + noff + koff);
            LDSM_X4(bl, aWl + noff + koff);
            int j0 = 2 * nt, j1 = j0 + 1;
            mma_bf16(acc[j0], ah, bh[0], bh[1]);
            mma_bf16(acc[j0], ah, bl[0], bl[1]);
            mma_bf16(acc[j0], al, bh[0], bh[1]);
            mma_bf16(acc[j1], ah, bh[2], bh[3]);
            mma_bf16(acc[j1], ah, bl[2], bl[3]);
            mma_bf16(acc[j1], al, bh[2], bh[3]);
        }
    }

    // epilogue: c0=(m,n) c1=(m,n+1) c2=(m+8,n) c3=(m+8,n+1)
    int colb = 2 * (lane & 3);
    int grow0 = row0 + m0 + (lane >> 2);
    int grow1 = grow0 + 8;
#pragma unroll
    for (int j = 0; j < 8; j++) {
        int col = n0 + j * 8 + colb;
        if (grow0 < n)
            *(float2*)&out[(size_t)grow0 * DD + col] =
                make_float2(acc[j][0], acc[j][1]);
        if (grow1 < n)
            *(float2*)&out[(size_t)grow1 * DD + col] =
                make_float2(acc[j][2], acc[j][3]);
    }
}

// ===========================================================================
// CSR gather: agg[v] = sum_{e in csr(v)} dinv[srcs[e]] * h[srcs[e]]
// ===========================================================================
template <bool FLAGGED>
__global__ void gather_kernel(const float4* __restrict__ h4,
                              float4* __restrict__ agg4, int n) {
    int v = (blockIdx.x * blockDim.x + threadIdx.x) >> 5;
    int lane = threadIdx.x & 31;
    if (v >= n) return;
    if (FLAGGED && !g_flag[v]) return;
    int beg = g_rowptr[v];
    int end = g_rowptr[v + 1];
    float4 acc = make_float4(0.f, 0.f, 0.f, 0.f);
    int i = beg;
    for (; i + 8 <= end; i += 8) {
        int s[8];
#pragma unroll
        for (int q = 0; q < 8; q++) s[q] = __ldg(&g_srcs[i + q]);
        float ds[8];
#pragma unroll
        for (int q = 0; q < 8; q++) ds[q] = __ldg(&g_dinv[s[q]]);
        float4 a[8];
#pragma unroll
        for (int q = 0; q < 8; q++) a[q] = __ldg(&h4[(size_t)s[q] * 32 + lane]);
#pragma unroll
        for (int q = 0; q < 8; q++) {
            acc.x += ds[q] * a[q].x; acc.y += ds[q] * a[q].y;
            acc.z += ds[q] * a[q].z; acc.w += ds[q] * a[q].w;
        }
    }
    for (; i < end; i++) {
        int s = __ldg(&g_srcs[i]);
        float ds = __ldg(&g_dinv[s]);
        float4 a = __ldg(&h4[(size_t)s * 32 + lane]);
        acc.x += ds * a.x; acc.y += ds * a.y;
        acc.z += ds * a.z; acc.w += ds * a.w;
    }
    agg4[(size_t)v * 32 + lane] = acc;
}

// ===========================================================================
// Scoring (relation-grouped, MMA): out[e] = zh^T W[r] zt
// ===========================================================================
__global__ __launch_bounds__(256, 1)
void score_kernel(const float* __restrict__ z,
                  const float* __restrict__ b2,
                  const int* __restrict__ head,
                  const int* __restrict__ tail,
                  float* __restrict__ out, int ES) {
    extern __shared__ __align__(16) char sm[];
    char* Zh = sm;                            // 64*272 bf16 hi
    char* Zl = sm + 17408;                    // 64*272 bf16 lo
    char* Wh = sm + 34816;                    // 128*272
    char* Wl = sm + 69632;                    // 128*272
    float* Zt = (float*)(sm + 104448);        // 64*128 f32
    float* Cc = (float*)(sm + 137216);        // 64*128 f32
    __shared__ int s_eid[64];
    __shared__ int s_head[64];
    __shared__ int s_tail[64];
    __shared__ __align__(16) float s_b2[DD];

    int r = blockIdx.x;
    int beg = g_off[r], end = g_off[r + 1];
    int base = beg + (int)blockIdx.y * 64;
    if (base >= end) return;
    int nb = min(64, end - base);
    int tid = threadIdx.x;

    {
        const float4* wh4 = (const float4*)(g_rwh + (size_t)r * IMG_U32);
        const float4* wl4 = (const float4*)(g_rwl + (size_t)r * IMG_U32);
        float4* dh = (float4*)Wh;
        float4* dl = (float4*)Wl;
#pragma unroll
        for (int i = 0; i < 9; i++) {
            int v = tid + i * 256;
            if (v < 2176) {
                dh[v] = __ldg(&wh4[v]);
                dl[v] = __ldg(&wl4[v]);
            }
        }
    }
    if (tid < DD) s_b2[tid] = b2[tid];
    if (tid < 64) {
        int e = -1, hh = 0, tt = 0;
        if (tid < nb) {
            e = g_bucket[base + tid];
            hh = __ldg(&head[e]);
            tt = __ldg(&tail[e]);
        }
        s_eid[tid] = e; s_head[tid] = hh; s_tail[tid] = tt;
    }
    __syncthreads();

    const float4* z4 = (const float4*)z;
    const float4* b24 = (const float4*)s_b2;
#pragma unroll
    for (int i = 0; i < 8; i++) {
        int v = tid + i * 256;
        int rr = v >> 5, c4 = v & 31;
        float4 ah = make_float4(0.f, 0.f, 0.f, 0.f);
        float4 at = make_float4(0.f, 0.f, 0.f, 0.f);
        if (rr < nb) {
            int hh = s_head[rr], tt = s_tail[rr];
            float dh_ = g_dinv[hh], dt_ = g_dinv[tt];
            float4 xh = __ldg(&z4[(size_t)hh * 32 + c4]);
            float4 xt = __ldg(&z4[(size_t)tt * 32 + c4]);
            float4 b = b24[c4];
            ah.x = dh_ * xh.x + b.x; ah.y = dh_ * xh.y + b.y;
            ah.z = dh_ * xh.z + b.z; ah.w = dh_ * xh.w + b.w;
            at.x = dt_ * xt.x + b.x; at.y = dt_ * xt.y + b.y;
            at.z = dt_ * xt.z + b.z; at.w = dt_ * xt.w + b.w;
        }
        u32 h0, l0, h1, l1;
        split_pack(ah.x, ah.y, h0, l0);
        split_pack(ah.z, ah.w, h1, l1);
        int boff = rr * 272 + c4 * 8;
        *(u64*)(Zh + boff) = (u64)h0 | ((u64)h1 << 32);
        *(u64*)(Zl + boff) = (u64)l0 | ((u64)l1 << 32);
        ((float4*)Zt)[v] = at;
    }
    __syncthreads();

    int w = tid >> 5;
    int lane = tid & 31;
    int wm = w >> 1;
    int wn = w & 1;
    int m0 = 16 * wm;
    int n0 = 64 * wn;

    int arow = (lane & 7) + (lane & 8);
    int acolb = (lane & 16);
    u32 aZh = smem_u32(Zh) + (m0 + arow) * 272 + acolb;
    u32 aZl = smem_u32(Zl) + (m0 + arow) * 272 + acolb;
    int brow = (lane & 7) + ((lane & 16) >> 1);
    int bcolb = (lane & 8) * 2;
    u32 aWh = smem_u32(Wh) + (n0 + brow) * 272 + bcolb;
    u32 aWl = smem_u32(Wl) + (n0 + brow) * 272 + bcolb;

    float acc[8][4];
#pragma unroll
    for (int t = 0; t < 8; t++)
#pragma unroll
        for (int q = 0; q < 4; q++) acc[t][q] = 0.f;

#pragma unroll
    for (int ks = 0; ks < 8; ks++) {
        u32 koff = ks * 32;
        u32 ah[4], al[4];
        LDSM_X4(ah, aZh + koff);
        LDSM_X4(al, aZl + koff);
#pragma unroll
        for (int nt = 0; nt < 4; nt++) {
            u32 noff = nt * 16 * 272;
            u32 bh[4], bl[4];
            LDSM_X4(bh, aWh + noff + koff);
            LDSM_X4(bl, aWl + noff + koff);
            int j0 = 2 * nt, j1 = j0 + 1;
            mma_bf16(acc[j0], ah, bh[0], bh[1]);
            mma_bf16(acc[j0], ah, bl[0], bl[1]);
            mma_bf16(acc[j0], al, bh[0], bh[1]);
            mma_bf16(acc[j1], ah, bh[2], bh[3]);
            mma_bf16(acc[j1], ah, bl[2], bl[3]);
            mma_bf16(acc[j1], al, bh[2], bh[3]);
        }
    }

    int mrow = m0 + (lane >> 2);
    int colb = 2 * (lane & 3);
#pragma unroll
    for (int j = 0; j < 8; j++) {
        int col = n0 + j * 8 + colb;
        *(float2*)&Cc[mrow * DD + col]       = make_float2(acc[j][0], acc[j][1]);
        *(float2*)&Cc[(mrow + 8) * DD + col] = make_float2(acc[j][2], acc[j][3]);
    }
    __syncthreads();

#pragma unroll
    for (int rr8 = 0; rr8 < 8; rr8++) {
        int row = w * 8 + rr8;
        float4 c = ((float4*)Cc)[row * 32 + lane];
        float4 t = ((float4*)Zt)[row * 32 + lane];
        float p = c.x * t.x + c.y * t.y + c.z * t.z + c.w * t.w;
#pragma unroll
        for (int off = 16; off; off >>= 1)
            p += __shfl_down_sync(0xffffffffu, p, off);
        if (lane == 0 && row < nb) out[s_eid[row]] = p;
    }
}

// ---------------------------------------------------------------------------
extern "C" void kernel_launch(void* const* d_in, const int* in_sizes, int n_in,
                              void* d_out, int out_size) {
    const float* x0   = (const float*)d_in[0];
    const float* W1   = (const float*)d_in[1];
    const float* b1   = (const float*)d_in[2];
    const float* W2   = (const float*)d_in[3];
    const float* b2   = (const float*)d_in[4];
    const float* relW = (const float*)d_in[5];
    const int*   ei   = (const int*)d_in[6];
    const int*   rel  = (const int*)d_in[7];
    const int*   head = (const int*)d_in[8];
    const int*   tail = (const int*)d_in[9];

    int N  = in_sizes[0] / DD;
    int E  = in_sizes[6] / 2;
    int ES = in_sizes[7];
    const int* src = ei;
    const int* dst = ei + E;

    float *h_p, *agg_p;
    int *deg_p, *cnt_p;
    unsigned char* flag_p;
    u32 *w1h_p, *w1l_p, *w2h_p, *w2l_p;
    cudaGetSymbolAddress((void**)&h_p, g_h);
    cudaGetSymbolAddress((void**)&agg_p, g_agg);
    cudaGetSymbolAddress((void**)&deg_p, g_deg);
    cudaGetSymbolAddress((void**)&cnt_p, g_cnt);
    cudaGetSymbolAddress((void**)&flag_p, g_flag);
    cudaGetSymbolAddress((void**)&w1h_p, g_w1h);
    cudaGetSymbolAddress((void**)&w1l_p, g_w1l);
    cudaGetSymbolAddress((void**)&w2h_p, g_w2h);
    cudaGetSymbolAddress((void**)&w2l_p, g_w2l);

    size_t gemm_smem = 3 * 34816;       // 102 KB (A 34K + W 68K)
    size_t score_smem = 169984;         // ~166 KB
    cudaFuncSetAttribute(score_kernel,
                         cudaFuncAttributeMaxDynamicSharedMemorySize, (int)score_smem);
    cudaFuncSetAttribute(gemm_mma_kernel<false>,
                         cudaFuncAttributeMaxDynamicSharedMemorySize, (int)gemm_smem);
    cudaFuncSetAttribute(gemm_mma_kernel<true>,
                         cudaFuncAttributeMaxDynamicSharedMemorySize, (int)gemm_smem);

    // side streams + events, created once on the first (non-capture) call
    struct Side {
        cudaStream_t s2, s3;
        cudaEvent_t evStart, evScan3, evPlace, evG1, evRelw;
        Side() {
            cudaStreamCreateWithFlags(&s2, cudaStreamNonBlocking);
            cudaStreamCreateWithFlags(&s3, cudaStreamNonBlocking);
            cudaEventCreateWithFlags(&evStart, cudaEventDisableTiming);
            cudaEventCreateWithFlags(&evScan3, cudaEventDisableTiming);
            cudaEventCreateWithFlags(&evPlace, cudaEventDisableTiming);
            cudaEventCreateWithFlags(&evG1, cudaEventDisableTiming);
            cudaEventCreateWithFlags(&evRelw, cudaEventDisableTiming);
        }
    };
    static Side side;

    int nchunks = (N + SCAN_CHUNK - 1) / SCAN_CHUNK;
    int nbE4 = (E + 1023) / 1024;
    int nbS4 = (ES + 1023) / 1024;
    int gemm_blocks = (N + 63) / 64;
    int gather_blocks = (N * 32 + 255) / 256;

    // fork side pipeline FIRST: W split -> GEMM1 -> relW split
    cudaEventRecord(side.evStart, 0);
    cudaStreamWaitEvent(side.s3, side.evStart, 0);
    prep_w_kernel<<<64, 256, 0, side.s3>>>(W1, W2);
    gemm_mma_kernel<false><<<gemm_blocks, 256, gemm_smem, side.s3>>>(
        x0, nullptr, w1h_p, w1l_p, h_p, N);
    cudaEventRecord(side.evG1, side.s3);
    prep_relw_kernel<<<512, 256, 0, side.s3>>>(relW);
    cudaEventRecord(side.evRelw, side.s3);

    // main stream: CSR front-end
    cudaMemsetAsync(deg_p, 0, (size_t)N * sizeof(int), 0);
    cudaMemsetAsync(cnt_p, 0, NREL * sizeof(int), 0);
    cudaMemsetAsync(flag_p, 0, (size_t)N, 0);
    prep_edges_kernel<<<nbE4 + nbS4, 256>>>(dst, E, rel, head, tail, ES);
    scan1_kernel<<<nchunks, 256>>>(N);
    scan2_kernel<<<1, 64>>>(nchunks, N);
    scan3_kernel<<<nchunks, 256>>>(N);

    // placement forked onto s2
    cudaEventRecord(side.evScan3, 0);
    cudaStreamWaitEvent(side.s2, side.evScan3, 0);
    place_kernel<<<nbE4 + nbS4, 256, 0, side.s2>>>(src, dst, E, rel, ES);
    cudaEventRecord(side.evPlace, side.s2);

    // join GEMM1 + place, then gather1 (dinv-weighted)
    cudaStreamWaitEvent(0, side.evG1, 0);
    cudaStreamWaitEvent(0, side.evPlace, 0);
    gather_kernel<false><<<gather_blocks, 256>>>((const float4*)h_p,
                                                 (float4*)agg_p, N);

    // layer 2: h2 = relu(dinv*agg + b1) @ W2 -> g_h
    gemm_mma_kernel<true><<<gemm_blocks, 256, gemm_smem>>>(
        agg_p, b1, w2h_p, w2l_p, h_p, N);

    // flagged gather2 (dinv-weighted): z rows -> g_agg
    gather_kernel<true><<<gather_blocks, 256>>>((const float4*)h_p,
                                                (float4*)agg_p, N);

    // join relW prep, then score (reads z from g_agg)
    cudaStreamWaitEvent(0, side.evRelw, 0);
    {
        dim3 grid(NREL, (ES + 63) / 64);
        score_kernel<<<grid, 256, score_smem>>>(agg_p, b2, head, tail,
                                                (float*)d_out, ES);
    }
}

// round 17
// speedup vs baseline: 1.1644x; 1.0386x over previous
#include <cuda_runtime.h>
#include <cuda_bf16.h>

#define DD 128
#define MAXN 100000
#define MAXE 1700000
#define MAXES 131072
#define NREL 16
#define SCAN_CHUNK 1024
#define MAX_CHUNKS ((MAXN + SCAN_CHUNK - 1) / SCAN_CHUNK)

#define WROW 136
#define IMG_U32 (DD * (WROW / 2))   // 8704 u32 per 128x136 bf16 image

typedef unsigned long long u64;
typedef unsigned int u32;

static __device__ __align__(16) float g_dinv[MAXN];
static __device__ __align__(256) float g_h[MAXN * DD];
static __device__ __align__(256) float g_agg[MAXN * DD];
static __device__ int g_deg[MAXN];
static __device__ int g_rowptr[MAXN + 1];
static __device__ int g_cur[MAXN];
static __device__ int g_srcs[MAXE];
static __device__ int g_blksum[MAX_CHUNKS];
static __device__ int g_cnt[NREL];
static __device__ int g_off[NREL + 1];
static __device__ int g_rcur[NREL];
static __device__ int g_bucket[MAXES];
static __device__ unsigned char g_flag[MAXN];
static __device__ __align__(16) u32 g_w1h[IMG_U32];
static __device__ __align__(16) u32 g_w1l[IMG_U32];
static __device__ __align__(16) u32 g_w2h[IMG_U32];
static __device__ __align__(16) u32 g_w2l[IMG_U32];
static __device__ __align__(16) u32 g_rwh[NREL * IMG_U32];
static __device__ __align__(16) u32 g_rwl[NREL * IMG_U32];

// ===========================================================================
// helpers
// ===========================================================================
__device__ __forceinline__ u32 smem_u32(const void* p) {
    u32 a;
    asm("{ .reg .u64 t; cvta.to.shared.u64 t, %1; cvt.u32.u64 %0, t; }"
        : "=r"(a) : "l"(p));
    return a;
}

#define LDSM_X4(r, addr) \
    asm volatile("ldmatrix.sync.aligned.m8n8.x4.shared.b16 {%0,%1,%2,%3}, [%4];" \
                 : "=r"((r)[0]), "=r"((r)[1]), "=r"((r)[2]), "=r"((r)[3]) \
                 : "r"(addr))

__device__ __forceinline__ void mma_bf16(float* c, const u32* a, u32 b0, u32 b1) {
    asm volatile(
        "mma.sync.aligned.m16n8k16.row.col.f32.bf16.bf16.f32 "
        "{%0,%1,%2,%3}, {%4,%5,%6,%7}, {%8,%9}, {%0,%1,%2,%3};"
        : "+f"(c[0]), "+f"(c[1]), "+f"(c[2]), "+f"(c[3])
        : "r"(a[0]), "r"(a[1]), "r"(a[2]), "r"(a[3]), "r"(b0), "r"(b1));
}

__device__ __forceinline__ void split_pack(float a0, float a1, u32& hi, u32& lo) {
    __nv_bfloat16 h0 = __float2bfloat16(a0);
    __nv_bfloat16 h1 = __float2bfloat16(a1);
    __nv_bfloat16 l0 = __float2bfloat16(a0 - __bfloat162float(h0));
    __nv_bfloat16 l1 = __float2bfloat16(a1 - __bfloat162float(h1));
    hi = (u32)__bfloat16_as_ushort(h0) | ((u32)__bfloat16_as_ushort(h1) << 16);
    lo = (u32)__bfloat16_as_ushort(l0) | ((u32)__bfloat16_as_ushort(l1) << 16);
}

// ===========================================================================
// prep (stream 0): deg count | rel count + flags
// ===========================================================================
__global__ void prep_edges_kernel(const int* __restrict__ dst, int E,
                                  const int* __restrict__ rel,
                                  const int* __restrict__ head,
                                  const int* __restrict__ tail, int ES) {
    int nbE = (E + 1023) / 1024;
    int b = blockIdx.x;
    int tid = threadIdx.x;
    if (b < nbE) {
#pragma unroll
        for (int i = 0; i < 4; i++) {
            int e = b * 1024 + i * 256 + tid;
            if (e < E) atomicAdd(&g_deg[dst[e]], 1);
        }
    } else {
#pragma unroll
        for (int i = 0; i < 4; i++) {
            int e = (b - nbE) * 1024 + i * 256 + tid;
            if (e < ES) {
                atomicAdd(&g_cnt[rel[e]], 1);
                g_flag[head[e]] = 1;
                g_flag[tail[e]] = 1;
            }
        }
    }
}

// W1/W2 split (side stream, feeds GEMM1/GEMM2)
__global__ void prep_w_kernel(const float* __restrict__ W1,
                              const float* __restrict__ W2) {
    int id = blockIdx.x * blockDim.x + threadIdx.x;  // 0..16383
    const float* W = (id < 8192) ? W1 : W2;
    u32* oh = (id < 8192) ? g_w1h : g_w2h;
    u32* ol = (id < 8192) ? g_w1l : g_w2l;
    int wi = id & 8191;
    int nrow = wi >> 6;
    int kp = wi & 63;
    int k = kp * 2;
    float a0 = W[k * DD + nrow];
    float a1 = W[(k + 1) * DD + nrow];
    u32 hi, lo;
    split_pack(a0, a1, hi, lo);
    int idx = nrow * (WROW / 2) + kp;
    oh[idx] = hi;
    ol[idx] = lo;
    if (kp < 4) {
        oh[nrow * (WROW / 2) + 64 + kp] = 0u;
        ol[nrow * (WROW / 2) + 64 + kp] = 0u;
    }
}

// relW split (side stream; only score consumes it)
__global__ void prep_relw_kernel(const float* __restrict__ relW) {
    int id = blockIdx.x * blockDim.x + threadIdx.x;  // 0..131071
    int r = id >> 13;
    int wi = id & 8191;
    int nrow = wi >> 6;
    int kp = wi & 63;
    int k = kp * 2;
    const float* W = relW + (size_t)r * DD * DD;
    float a0 = W[k * DD + nrow];
    float a1 = W[(k + 1) * DD + nrow];
    u32 hi, lo;
    split_pack(a0, a1, hi, lo);
    int idx = r * IMG_U32 + nrow * (WROW / 2) + kp;
    g_rwh[idx] = hi;
    g_rwl[idx] = lo;
    if (kp < 4) {
        g_rwh[r * IMG_U32 + nrow * (WROW / 2) + 64 + kp] = 0u;
        g_rwl[r * IMG_U32 + nrow * (WROW / 2) + 64 + kp] = 0u;
    }
}

// ===========================================================================
// Scan kernels for CSR rowptr (+ relation prefix folded into scan2)
// ===========================================================================
__global__ void scan1_kernel(int n) {
    __shared__ int wsum[8];
    int chunk = blockIdx.x;
    int tid = threadIdx.x;
    int s = 0;
#pragma unroll
    for (int i = 0; i < 4; i++) {
        int idx = chunk * SCAN_CHUNK + tid + i * 256;
        if (idx < n) s += g_deg[idx];
    }
#pragma unroll
    for (int off = 16; off; off >>= 1) s += __shfl_down_sync(0xffffffffu, s, off);
    if ((tid & 31) == 0) wsum[tid >> 5] = s;
    __syncthreads();
    if (tid == 0) {
        int a = 0;
#pragma unroll
        for (int i = 0; i < 8; i++) a += wsum[i];
        g_blksum[chunk] = a;
    }
}

__global__ void scan2_kernel(int nchunks, int n) {
    int tid = threadIdx.x;
    if (tid < 32) {
        int v[4];
        int s = 0;
#pragma unroll
        for (int j = 0; j < 4; j++) {
            int idx = tid * 4 + j;
            v[j] = (idx < nchunks) ? g_blksum[idx] : 0;
            s += v[j];
        }
        int pre = s;
#pragma unroll
        for (int off = 1; off < 32; off <<= 1) {
            int t = __shfl_up_sync(0xffffffffu, pre, off);
            if (tid >= off) pre += t;
        }
        int run = pre - s;
#pragma unroll
        for (int j = 0; j < 4; j++) {
            int idx = tid * 4 + j;
            if (idx < nchunks) g_blksum[idx] = run;
            run += v[j];
        }
        if (tid == 31) g_rowptr[n] = run;
    } else if (tid == 32) {
        int acc = 0;
        for (int i = 0; i < NREL; i++) {
            g_off[i] = acc;
            g_rcur[i] = acc;
            acc += g_cnt[i];
        }
        g_off[NREL] = acc;
    }
}

__global__ void scan3_kernel(int n) {
    __shared__ int wsum[8];
    int chunk = blockIdx.x;
    int tid = threadIdx.x;
    int lane = tid & 31, w = tid >> 5;
    int base0 = chunk * SCAN_CHUNK + tid * 4;
    int v[4];
    int s = 0;
#pragma unroll
    for (int j = 0; j < 4; j++) {
        int idx = base0 + j;
        v[j] = (idx < n) ? g_deg[idx] : 0;
        s += v[j];
    }
    int pre = s;
#pragma unroll
    for (int off = 1; off < 32; off <<= 1) {
        int t = __shfl_up_sync(0xffffffffu, pre, off);
        if (lane >= off) pre += t;
    }
    if (lane == 31) wsum[w] = pre;
    __syncthreads();
    if (tid == 0) {
        int a = 0;
#pragma unroll
        for (int i = 0; i < 8; i++) { int t = wsum[i]; wsum[i] = a; a += t; }
    }
    __syncthreads();
    int excl = pre - s + wsum[w] + g_blksum[chunk];
#pragma unroll
    for (int j = 0; j < 4; j++) {
        int idx = base0 + j;
        if (idx < n) {
            g_rowptr[idx] = excl;
            g_cur[idx] = excl;
            g_dinv[idx] = (v[j] > 0) ? rsqrtf((float)v[j]) : 0.0f;
            excl += v[j];
        }
    }
}

// fused: CSR placement | relation bucket placement (4 items / thread)
__global__ void place_kernel(const int* __restrict__ src,
                             const int* __restrict__ dst, int E,
                             const int* __restrict__ rel, int ES) {
    int nbE = (E + 1023) / 1024;
    int b = blockIdx.x;
    int tid = threadIdx.x;
    if (b < nbE) {
#pragma unroll
        for (int i = 0; i < 4; i++) {
            int e = b * 1024 + i * 256 + tid;
            if (e < E) {
                int pos = atomicAdd(&g_cur[dst[e]], 1);
                g_srcs[pos] = src[e];
            }
        }
    } else {
#pragma unroll
        for (int i = 0; i < 4; i++) {
            int e = (b - nbE) * 1024 + i * 256 + tid;
            if (e < ES) {
                int pos = atomicAdd(&g_rcur[rel[e]], 1);
                g_bucket[pos] = e;
            }
        }
    }
}

// ===========================================================================
// Tensor-core GEMM (mma.sync, bf16 3-pass split).
// 64-row tiles, 2 CTAs/SM: block B's staging overlaps block A's MMA.
// 8 warps, warp tile 16m x 64n (4x2 grid).
// FUSE_IN: a -> relu(dinv[row]*a + b1).
// ===========================================================================
template <bool FUSE_IN>
__global__ __launch_bounds__(256, 2)
void gemm_mma_kernel(const float* __restrict__ A, const float* __restrict__ bias,
                     const u32* __restrict__ WhImg, const u32* __restrict__ WlImg,
                     float* __restrict__ out, int n) {
    extern __shared__ __align__(16) char sm[];
    char* Ah = sm;                        // 64*272 = 17408
    char* Al = sm + 17408;
    char* Wh = sm + 34816;                // 128*272 = 34816
    char* Wl = sm + 69632;

    int tid = threadIdx.x;
    {
        const float4* wh4 = (const float4*)WhImg;
        const float4* wl4 = (const float4*)WlImg;
        float4* dh = (float4*)Wh;
        float4* dl = (float4*)Wl;
#pragma unroll
        for (int i = 0; i < 9; i++) {
            int v = tid + i * 256;
            if (v < 2176) {
                dh[v] = wh4[v];
                dl[v] = wl4[v];
            }
        }
    }

    int row0 = blockIdx.x * 64;
#pragma unroll
    for (int i = 0; i < 8; i++) {
        int v = tid + i * 256;          // 0..2047
        int r = v >> 5;                 // row in tile (0..63)
        int c4 = v & 31;
        int grow = row0 + r;
        float4 a = make_float4(0.f, 0.f, 0.f, 0.f);
        if (grow < n) {
            a = ((const float4*)A)[(size_t)grow * 32 + c4];
            if (FUSE_IN) {
                float di = g_dinv[grow];
                int c = c4 * 4;
                a.x = fmaxf(di * a.x + bias[c + 0], 0.f);
                a.y = fmaxf(di * a.y + bias[c + 1], 0.f);
                a.z = fmaxf(di * a.z + bias[c + 2], 0.f);
                a.w = fmaxf(di * a.w + bias[c + 3], 0.f);
            }
        }
        u32 h0, l0, h1, l1;
        split_pack(a.x, a.y, h0, l0);
        split_pack(a.z, a.w, h1, l1);
        int boff = r * 272 + c4 * 8;
        *(u64*)(Ah + boff) = (u64)h0 | ((u64)h1 << 32);
        *(u64*)(Al + boff) = (u64)l0 | ((u64)l1 << 32);
    }
    __syncthreads();

    int w = tid >> 5;
    int lane = tid & 31;
    int wm = w >> 1;   // 0..3 -> m-strip of 16
    int wn = w & 1;    // 0..1 -> n-strip of 64
    int m0 = 16 * wm;
    int n0 = 64 * wn;

    int arow = (lane & 7) + (lane & 8);
    int acolb = (lane & 16);
    u32 aAh = smem_u32(Ah) + (m0 + arow) * 272 + acolb;
    u32 aAl = smem_u32(Al) + (m0 + arow) * 272 + acolb;
    int brow = (lane & 7) + ((lane & 16) >> 1);
    int bcolb = (lane & 8) * 2;
    u32 aWh = smem_u32(Wh) + (n0 + brow) * 272 + bcolb;
    u32 aWl = smem_u32(Wl) + (n0 + brow) * 272 + bcolb;

    float acc[8][4];
#pragma unroll
    for (int t = 0; t < 8; t++)
#pragma unroll
        for (int q = 0; q < 4; q++) acc[t][q] = 0.f;

#pragma unroll
    for (int ks = 0; ks < 8; ks++) {
        u32 koff = ks * 32;
        u32 ah[4], al[4];
        LDSM_X4(ah, aAh + koff);
        LDSM_X4(al, aAl + koff);
#pragma unroll
        for (int nt = 0; nt < 4; nt++) {
            u32 noff = nt * 16 * 272;
            u32 bh[4], bl[4];
            LDSM_X4(bh, aWh + noff + koff);
            LDSM_X4(bl, aWl + noff + koff);
            int j0 = 2 * nt, j1 = j0 + 1;
            mma_bf16(acc[j0], ah, bh[0], bh[1]);
            mma_bf16(acc[j0], ah, bl[0], bl[1]);
            mma_bf16(acc[j0], al, bh[0], bh[1]);
            mma_bf16(acc[j1], ah, bh[2], bh[3]);
            mma_bf16(acc[j1], ah, bl[2], bl[3]);
            mma_bf16(acc[j1], al, bh[2], bh[3]);
        }
    }

    // epilogue: c0=(m,n) c1=(m,n+1) c2=(m+8,n) c3=(m+8,n+1)
    int colb = 2 * (lane & 3);
    int grow0 = row0 + m0 + (lane >> 2);
    int grow1 = grow0 + 8;
#pragma unroll
    for (int j = 0; j < 8; j++) {
        int col = n0 + j * 8 + colb;
        if (grow0 < n)
            *(float2*)&out[(size_t)grow0 * DD + col] =
                make_float2(acc[j][0], acc[j][1]);
        if (grow1 < n)
            *(float2*)&out[(size_t)grow1 * DD + col] =
                make_float2(acc[j][2], acc[j][3]);
    }
}

// ===========================================================================
// CSR gather: agg[v] = sum_{e in csr(v)} dinv[srcs[e]] * h[srcs[e]]
// ===========================================================================
template <bool FLAGGED>
__global__ void gather_kernel(const float4* __restrict__ h4,
                              float4* __restrict__ agg4, int n) {
    int v = (blockIdx.x * blockDim.x + threadIdx.x) >> 5;
    int lane = threadIdx.x & 31;
    if (v >= n) return;
    if (FLAGGED && !g_flag[v]) return;
    int beg = g_rowptr[v];
    int end = g_rowptr[v + 1];
    float4 acc = make_float4(0.f, 0.f, 0.f, 0.f);
    int i = beg;
    for (; i + 8 <= end; i += 8) {
        int s[8];
#pragma unroll
        for (int q = 0; q < 8; q++) s[q] = __ldg(&g_srcs[i + q]);
        float ds[8];
#pragma unroll
        for (int q = 0; q < 8; q++) ds[q] = __ldg(&g_dinv[s[q]]);
        float4 a[8];
#pragma unroll
        for (int q = 0; q < 8; q++) a[q] = __ldg(&h4[(size_t)s[q] * 32 + lane]);
#pragma unroll
        for (int q = 0; q < 8; q++) {
            acc.x += ds[q] * a[q].x; acc.y += ds[q] * a[q].y;
            acc.z += ds[q] * a[q].z; acc.w += ds[q] * a[q].w;
        }
    }
    for (; i < end; i++) {
        int s = __ldg(&g_srcs[i]);
        float ds = __ldg(&g_dinv[s]);
        float4 a = __ldg(&h4[(size_t)s * 32 + lane]);
        acc.x += ds * a.x; acc.y += ds * a.y;
        acc.z += ds * a.z; acc.w += ds * a.w;
    }
    agg4[(size_t)v * 32 + lane] = acc;
}

// ===========================================================================
// Scoring (relation-grouped, MMA): out[e] = zh^T W[r] zt
// 2 CTAs/SM: C fragments alias the (dead-after-mainloop) Wh region; zt is
// recomputed from global in the final dot instead of staged in smem.
// ===========================================================================
__global__ __launch_bounds__(256, 2)
void score_kernel(const float* __restrict__ z,
                  const float* __restrict__ b2,
                  const int* __restrict__ head,
                  const int* __restrict__ tail,
                  float* __restrict__ out, int ES) {
    extern __shared__ __align__(16) char sm[];
    char* Zh = sm;                            // 64*272 bf16 hi
    char* Zl = sm + 17408;                    // 64*272 bf16 lo
    char* Wh = sm + 34816;                    // 128*272
    char* Wl = sm + 69632;                    // 128*272
    float* Cc = (float*)(sm + 34816);         // aliases Wh after mainloop
    __shared__ int s_eid[64];
    __shared__ int s_head[64];
    __shared__ int s_tail[64];
    __shared__ __align__(16) float s_b2[DD];

    int r = blockIdx.x;
    int beg = g_off[r], end = g_off[r + 1];
    int base = beg + (int)blockIdx.y * 64;
    if (base >= end) return;
    int nb = min(64, end - base);
    int tid = threadIdx.x;

    {
        const float4* wh4 = (const float4*)(g_rwh + (size_t)r * IMG_U32);
        const float4* wl4 = (const float4*)(g_rwl + (size_t)r * IMG_U32);
        float4* dh = (float4*)Wh;
        float4* dl = (float4*)Wl;
#pragma unroll
        for (int i = 0; i < 9; i++) {
            int v = tid + i * 256;
            if (v < 2176) {
                dh[v] = __ldg(&wh4[v]);
                dl[v] = __ldg(&wl4[v]);
            }
        }
    }
    if (tid < DD) s_b2[tid] = b2[tid];
    if (tid < 64) {
        int e = -1, hh = 0, tt = 0;
        if (tid < nb) {
            e = g_bucket[base + tid];
            hh = __ldg(&head[e]);
            tt = __ldg(&tail[e]);
        }
        s_eid[tid] = e; s_head[tid] = hh; s_tail[tid] = tt;
    }
    __syncthreads();

    // stage zh (bf16 split); zt is recomputed later from global
    const float4* z4 = (const float4*)z;
    const float4* b24 = (const float4*)s_b2;
#pragma unroll
    for (int i = 0; i < 8; i++) {
        int v = tid + i * 256;
        int rr = v >> 5, c4 = v & 31;
        float4 ah = make_float4(0.f, 0.f, 0.f, 0.f);
        if (rr < nb) {
            int hh = s_head[rr];
            float dh_ = g_dinv[hh];
            float4 xh = __ldg(&z4[(size_t)hh * 32 + c4]);
            float4 b = b24[c4];
            ah.x = dh_ * xh.x + b.x; ah.y = dh_ * xh.y + b.y;
            ah.z = dh_ * xh.z + b.z; ah.w = dh_ * xh.w + b.w;
        }
        u32 h0, l0, h1, l1;
        split_pack(ah.x, ah.y, h0, l0);
        split_pack(ah.z, ah.w, h1, l1);
        int boff = rr * 272 + c4 * 8;
        *(u64*)(Zh + boff) = (u64)h0 | ((u64)h1 << 32);
        *(u64*)(Zl + boff) = (u64)l0 | ((u64)l1 << 32);
    }
    __syncthreads();

    int w = tid >> 5;
    int lane = tid & 31;
    int wm = w >> 1;
    int wn = w & 1;
    int m0 = 16 * wm;
    int n0 = 64 * wn;

    int arow = (lane & 7) + (lane & 8);
    int acolb = (lane & 16);
    u32 aZh = smem_u32(Zh) + (m0 + arow) * 272 + acolb;
    u32 aZl = smem_u32(Zl) + (m0 + arow) * 272 + acolb;
    int brow = (lane & 7) + ((lane & 16) >> 1);
    int bcolb = (lane & 8) * 2;
    u32 aWh = smem_u32(Wh) + (n0 + brow) * 272 + bcolb;
    u32 aWl = smem_u32(Wl) + (n0 + brow) * 272 + bcolb;

    float acc[8][4];
#pragma unroll
    for (int t = 0; t < 8; t++)
#pragma unroll
        for (int q = 0; q < 4; q++) acc[t][q] = 0.f;

#pragma unroll
    for (int ks = 0; ks < 8; ks++) {
        u32 koff = ks * 32;
        u32 ah[4], al[4];
        LDSM_X4(ah, aZh + koff);
        LDSM_X4(al, aZl + koff);
#pragma unroll
        for (int nt = 0; nt < 4; nt++) {
            u32 noff = nt * 16 * 272;
            u32 bh[4], bl[4];
            LDSM_X4(bh, aWh + noff + koff);
            LDSM_X4(bl, aWl + noff + koff);
            int j0 = 2 * nt, j1 = j0 + 1;
            mma_bf16(acc[j0], ah, bh[0], bh[1]);
            mma_bf16(acc[j0], ah, bl[0], bl[1]);
            mma_bf16(acc[j0], al, bh[0], bh[1]);
            mma_bf16(acc[j1], ah, bh[2], bh[3]);
            mma_bf16(acc[j1], ah, bl[2], bl[3]);
            mma_bf16(acc[j1], al, bh[2], bh[3]);
        }
    }

    // Wh is dead; alias Cc onto it (barrier-protected)
    __syncthreads();

    int mrow = m0 + (lane >> 2);
    int colb = 2 * (lane & 3);
#pragma unroll
    for (int j = 0; j < 8; j++) {
        int col = n0 + j * 8 + colb;
        *(float2*)&Cc[mrow * DD + col]       = make_float2(acc[j][0], acc[j][1]);
        *(float2*)&Cc[(mrow + 8) * DD + col] = make_float2(acc[j][2], acc[j][3]);
    }
    __syncthreads();

    // final dot: zt recomputed from global (L2-hot)
#pragma unroll
    for (int rr8 = 0; rr8 < 8; rr8++) {
        int row = w * 8 + rr8;
        float4 c = ((float4*)Cc)[row * 32 + lane];
        int tt = s_tail[row];
        float dt_ = g_dinv[tt];
        float4 xt = __ldg(&z4[(size_t)tt * 32 + lane]);
        float4 b = b24[lane];
        float p = c.x * (dt_ * xt.x + b.x) + c.y * (dt_ * xt.y + b.y) +
                  c.z * (dt_ * xt.z + b.z) + c.w * (dt_ * xt.w + b.w);
#pragma unroll
        for (int off = 16; off; off >>= 1)
            p += __shfl_down_sync(0xffffffffu, p, off);
        if (lane == 0 && row < nb) out[s_eid[row]] = p;
    }
}

// ---------------------------------------------------------------------------
extern "C" void kernel_launch(void* const* d_in, const int* in_sizes, int n_in,
                              void* d_out, int out_size) {
    const float* x0   = (const float*)d_in[0];
    const float* W1   = (const float*)d_in[1];
    const float* b1   = (const float*)d_in[2];
    const float* W2   = (const float*)d_in[3];
    const float* b2   = (const float*)d_in[4];
    const float* relW = (const float*)d_in[5];
    const int*   ei   = (const int*)d_in[6];
    const int*   rel  = (const int*)d_in[7];
    const int*   head = (const int*)d_in[8];
    const int*   tail = (const int*)d_in[9];

    int N  = in_sizes[0] / DD;
    int E  = in_sizes[6] / 2;
    int ES = in_sizes[7];
    const int* src = ei;
    const int* dst = ei + E;

    float *h_p, *agg_p;
    int *deg_p, *cnt_p;
    unsigned char* flag_p;
    u32 *w1h_p, *w1l_p, *w2h_p, *w2l_p;
    cudaGetSymbolAddress((void**)&h_p, g_h);
    cudaGetSymbolAddress((void**)&agg_p, g_agg);
    cudaGetSymbolAddress((void**)&deg_p, g_deg);
    cudaGetSymbolAddress((void**)&cnt_p, g_cnt);
    cudaGetSymbolAddress((void**)&flag_p, g_flag);
    cudaGetSymbolAddress((void**)&w1h_p, g_w1h);
    cudaGetSymbolAddress((void**)&w1l_p, g_w1l);
    cudaGetSymbolAddress((void**)&w2h_p, g_w2h);
    cudaGetSymbolAddress((void**)&w2l_p, g_w2l);

    size_t gemm_smem = 3 * 34816;       // 102 KB (A 34K + W 68K)
    size_t score_smem = 4 * 34816;      // 136 KB? no: Zh+Zl+Wh+Wl = 104448
    score_smem = 104448;                // ~102 KB -> 2 CTAs/SM
    cudaFuncSetAttribute(score_kernel,
                         cudaFuncAttributeMaxDynamicSharedMemorySize, (int)score_smem);
    cudaFuncSetAttribute(gemm_mma_kernel<false>,
                         cudaFuncAttributeMaxDynamicSharedMemorySize, (int)gemm_smem);
    cudaFuncSetAttribute(gemm_mma_kernel<true>,
                         cudaFuncAttributeMaxDynamicSharedMemorySize, (int)gemm_smem);

    // side streams + events, created once on the first (non-capture) call
    struct Side {
        cudaStream_t s2, s3;
        cudaEvent_t evStart, evScan3, evPlace, evG1, evRelw;
        Side() {
            cudaStreamCreateWithFlags(&s2, cudaStreamNonBlocking);
            cudaStreamCreateWithFlags(&s3, cudaStreamNonBlocking);
            cudaEventCreateWithFlags(&evStart, cudaEventDisableTiming);
            cudaEventCreateWithFlags(&evScan3, cudaEventDisableTiming);
            cudaEventCreateWithFlags(&evPlace, cudaEventDisableTiming);
            cudaEventCreateWithFlags(&evG1, cudaEventDisableTiming);
            cudaEventCreateWithFlags(&evRelw, cudaEventDisableTiming);
        }
    };
    static Side side;

    int nchunks = (N + SCAN_CHUNK - 1) / SCAN_CHUNK;
    int nbE4 = (E + 1023) / 1024;
    int nbS4 = (ES + 1023) / 1024;
    int gemm_blocks = (N + 63) / 64;
    int gather_blocks = (N * 32 + 255) / 256;

    // fork side pipeline FIRST: W split -> GEMM1 -> relW split
    cudaEventRecord(side.evStart, 0);
    cudaStreamWaitEvent(side.s3, side.evStart, 0);
    prep_w_kernel<<<64, 256, 0, side.s3>>>(W1, W2);
    gemm_mma_kernel<false><<<gemm_blocks, 256, gemm_smem, side.s3>>>(
        x0, nullptr, w1h_p, w1l_p, h_p, N);
    cudaEventRecord(side.evG1, side.s3);
    prep_relw_kernel<<<512, 256, 0, side.s3>>>(relW);
    cudaEventRecord(side.evRelw, side.s3);

    // main stream: CSR front-end
    cudaMemsetAsync(deg_p, 0, (size_t)N * sizeof(int), 0);
    cudaMemsetAsync(cnt_p, 0, NREL * sizeof(int), 0);
    cudaMemsetAsync(flag_p, 0, (size_t)N, 0);
    prep_edges_kernel<<<nbE4 + nbS4, 256>>>(dst, E, rel, head, tail, ES);
    scan1_kernel<<<nchunks, 256>>>(N);
    scan2_kernel<<<1, 64>>>(nchunks, N);
    scan3_kernel<<<nchunks, 256>>>(N);

    // placement forked onto s2
    cudaEventRecord(side.evScan3, 0);
    cudaStreamWaitEvent(side.s2, side.evScan3, 0);
    place_kernel<<<nbE4 + nbS4, 256, 0, side.s2>>>(src, dst, E, rel, ES);
    cudaEventRecord(side.evPlace, side.s2);

    // join GEMM1 + place, then gather1 (dinv-weighted)
    cudaStreamWaitEvent(0, side.evG1, 0);
    cudaStreamWaitEvent(0, side.evPlace, 0);
    gather_kernel<false><<<gather_blocks, 256>>>((const float4*)h_p,
                                                 (float4*)agg_p, N);

    // layer 2: h2 = relu(dinv*agg + b1) @ W2 -> g_h
    gemm_mma_kernel<true><<<gemm_blocks, 256, gemm_smem>>>(
        agg_p, b1, w2h_p, w2l_p, h_p, N);

    // flagged gather2 (dinv-weighted): z rows -> g_agg
    gather_kernel<true><<<gather_blocks, 256>>>((const float4*)h_p,
                                                (float4*)agg_p, N);

    // join relW prep, then score (reads z from g_agg)
    cudaStreamWaitEvent(0, side.evRelw, 0);
    {
        dim3 grid(NREL, (ES + 63) / 64);
        score_kernel<<<grid, 256, score_smem>>>(agg_p, b2, head, tail,
                                                (float*)d_out, ES);
    }
}